// round 13
// baseline (speedup 1.0000x reference)
#include <cuda_runtime.h>
#include <math.h>

#define TOKENS 8192
#define DIMX   1024
#define HEADS  8
#define NKEYS  128
#define DKEY   512
#define DINNER 2048

// ---------------- scratch (device globals; no allocation allowed) ----------------
__device__ float g_WqT[(size_t)DIMX * 8192];        // 32 MB  (Wq transposed: [1024, 8192])
__device__ float g_Mmat[(size_t)2048 * DIMX];       // 8 MB   (combined key-query matrix)
__device__ float g_sim[(size_t)TOKENS * 2048];      // 64 MB
__device__ float g_hid[(size_t)TOKENS * DINNER];    // 64 MB  (hidden GEMM out, then gelu'd hidden)
__device__ float g_gate[TOKENS * HEADS];
__device__ int   g_idx[TOKENS * HEADS];

// ---------------- helpers ----------------
// 3xTF32 split: f = hi + lo with hi,lo tf32-representable; residual error ~2^-22.
__device__ __forceinline__ void split_tf32(float f, unsigned& hi, unsigned& lo) {
    asm("cvt.rna.tf32.f32 %0, %1;" : "=r"(hi) : "f"(f));
    float r = f - __uint_as_float(hi);   // exact in fp32
    asm("cvt.rna.tf32.f32 %0, %1;" : "=r"(lo) : "f"(r));
}
__device__ __forceinline__ unsigned f2t(float f) {
    unsigned u; asm("cvt.rna.tf32.f32 %0, %1;" : "=r"(u) : "f"(f)); return u;
}
__device__ __forceinline__ void mma8(float c[4], const unsigned a[4], const unsigned b[2]) {
    asm volatile(
        "mma.sync.aligned.m16n8k8.row.col.f32.tf32.tf32.f32 "
        "{%0,%1,%2,%3},{%4,%5,%6,%7},{%8,%9},{%0,%1,%2,%3};"
        : "+f"(c[0]), "+f"(c[1]), "+f"(c[2]), "+f"(c[3])
        : "r"(a[0]), "r"(a[1]), "r"(a[2]), "r"(a[3]), "r"(b[0]), "r"(b[1]));
}

// ---------------- K0: transpose Wq [8192,1024] -> WqT [1024,8192] ----------------
__global__ void k_transpose(const float* __restrict__ src, float* __restrict__ dst) {
    __shared__ float tile[32][33];
    int bx = blockIdx.x * 32, by = blockIdx.y * 32;
    int tx = threadIdx.x, ty = threadIdx.y;   // 32 x 8
#pragma unroll
    for (int j = 0; j < 32; j += 8)
        tile[ty + j][tx] = src[(size_t)(by + ty + j) * 1024 + bx + tx];
    __syncthreads();
#pragma unroll
    for (int j = 0; j < 32; j += 8)
        dst[(size_t)(bx + ty + j) * 8192 + by + tx] = tile[tx][ty + j];
}

// ---------------- NSxTF32 NT GEMM: C[M,N] = A[M,K] * B[N,K]^T --------------------
// BM=BN=128, BK=32, 512 threads (16 warps, 4x4), warp tile 32x32 (m16n8k8).
// STATIC smem (36KB), fp32 tiles, reader-side hi/lo split (proven R6 chassis).
// NS=3: hh + hl + lh  (routing path, fp32-level accuracy)
// NS=2: hh + hl       (value path, ~2.8e-4 rel; A lo split+mma skipped)
// special==1: batched key->M precompute. z = p*8+h.
template<int NS>
__global__ __launch_bounds__(512, 1)
void k_gemm_nt(const float* __restrict__ A, int lda,
               const float* __restrict__ B, int ldb,
               float* __restrict__ C, int ldc,
               int K, int special) {
    __shared__ float As[128][36];
    __shared__ float Bs[128][36];
    int tid  = threadIdx.x;
    int lane = tid & 31, wid = tid >> 5;
    int g = lane >> 2, tg = lane & 3;
    int wm = (wid >> 2) * 32, wn = (wid & 3) * 32;

    size_t aOff = 0, bOff = 0, cOff = 0;
    if (special) {
        int z = blockIdx.z;                       // z = p*8 + h
        aOff = (size_t)(z & 7) * (128 * 2 * 512)  // head offset in keys
             + (size_t)(z >> 3) * 512;            // p offset
        bOff = (size_t)z * 512;                   // column block in WqT
        cOff = (size_t)z * (128 * 1024);          // row block in Mmat
    }
    const float* Ab = A + aOff + (size_t)(blockIdx.y * 128) * lda;
    const float* Bb = B + bOff + (size_t)(blockIdx.x * 128) * ldb;

    int r0 = tid >> 3;            // 0..63 ; second element at r0+64
    int c0 = (tid & 7) * 4;       // 0..28

    float4 pa0 = *(const float4*)(Ab + (size_t)r0 * lda + c0);
    float4 pa1 = *(const float4*)(Ab + (size_t)(r0 + 64) * lda + c0);
    float4 pb0 = *(const float4*)(Bb + (size_t)r0 * ldb + c0);
    float4 pb1 = *(const float4*)(Bb + (size_t)(r0 + 64) * ldb + c0);

    float acc[2][4][4];
#pragma unroll
    for (int i = 0; i < 2; i++)
#pragma unroll
        for (int j = 0; j < 4; j++)
#pragma unroll
            for (int k = 0; k < 4; k++) acc[i][j][k] = 0.f;

    int KT = K >> 5;
    for (int kt = 0; kt < KT; kt++) {
        *(float4*)&As[r0][c0]      = pa0;
        *(float4*)&As[r0 + 64][c0] = pa1;
        *(float4*)&Bs[r0][c0]      = pb0;
        *(float4*)&Bs[r0 + 64][c0] = pb1;
        __syncthreads();

        if (kt + 1 < KT) {        // prefetch next tile; overlaps with compute below
            const float* Ap = Ab + (size_t)(kt + 1) * 32;
            const float* Bp = Bb + (size_t)(kt + 1) * 32;
            pa0 = *(const float4*)(Ap + (size_t)r0 * lda + c0);
            pa1 = *(const float4*)(Ap + (size_t)(r0 + 64) * lda + c0);
            pb0 = *(const float4*)(Bp + (size_t)r0 * ldb + c0);
            pb1 = *(const float4*)(Bp + (size_t)(r0 + 64) * ldb + c0);
        }

#pragma unroll
        for (int ks = 0; ks < 4; ks++) {
            int k0 = ks * 8;
            unsigned ah[2][4], al[2][4], bh[4][2], bl[4][2];
#pragma unroll
            for (int mt = 0; mt < 2; mt++) {
                int rr = wm + mt * 16 + g;
                if (NS >= 3) {
                    split_tf32(As[rr][k0 + tg],         ah[mt][0], al[mt][0]);
                    split_tf32(As[rr + 8][k0 + tg],     ah[mt][1], al[mt][1]);
                    split_tf32(As[rr][k0 + tg + 4],     ah[mt][2], al[mt][2]);
                    split_tf32(As[rr + 8][k0 + tg + 4], ah[mt][3], al[mt][3]);
                } else {
                    ah[mt][0] = f2t(As[rr][k0 + tg]);
                    ah[mt][1] = f2t(As[rr + 8][k0 + tg]);
                    ah[mt][2] = f2t(As[rr][k0 + tg + 4]);
                    ah[mt][3] = f2t(As[rr + 8][k0 + tg + 4]);
                }
            }
#pragma unroll
            for (int nt = 0; nt < 4; nt++) {
                int nn = wn + nt * 8 + g;
                split_tf32(Bs[nn][k0 + tg],     bh[nt][0], bl[nt][0]);
                split_tf32(Bs[nn][k0 + tg + 4], bh[nt][1], bl[nt][1]);
            }
#pragma unroll
            for (int mt = 0; mt < 2; mt++)
#pragma unroll
                for (int nt = 0; nt < 4; nt++) {
                    mma8(acc[mt][nt], ah[mt], bh[nt]);                 // hi*hi
                    mma8(acc[mt][nt], ah[mt], bl[nt]);                 // hi*lo
                    if (NS >= 3) mma8(acc[mt][nt], al[mt], bh[nt]);    // lo*hi
                }
        }
        __syncthreads();
    }

    float* Cb = C + cOff + (size_t)(blockIdx.y * 128) * ldc + blockIdx.x * 128;
#pragma unroll
    for (int mt = 0; mt < 2; mt++)
#pragma unroll
        for (int nt = 0; nt < 4; nt++) {
            int rr = wm + mt * 16 + g;
            int cc = wn + nt * 8 + 2 * tg;
            *(float2*)(Cb + (size_t)rr * ldc + cc) =
                make_float2(acc[mt][nt][0], acc[mt][nt][1]);
            *(float2*)(Cb + (size_t)(rr + 8) * ldc + cc) =
                make_float2(acc[mt][nt][2], acc[mt][nt][3]);
        }
}

// ---------------- K3: argmax over 128 keys per (t,h,p); gate + expert index ------
// top1 of (sx_i+sy_j) over the 16x16 topk cross product == max(sx)+max(sy).
__global__ void k_argmax(const float* __restrict__ sim,
                         float* __restrict__ gate, int* __restrict__ idxE) {
    int gw = (blockIdx.x * blockDim.x + threadIdx.x) >> 5;
    int lane = threadIdx.x & 31;
    if (gw >= TOKENS * HEADS) return;
    int t = gw >> 3, h = gw & 7;
    const float* p0 = sim + (size_t)t * 2048 + h * 128;
    float m[2]; int mi[2];
#pragma unroll
    for (int p = 0; p < 2; p++) {
        const float4 v = *(const float4*)(p0 + p * 1024 + lane * 4);
        float mv = v.x; int ix = lane * 4;
        if (v.y > mv) { mv = v.y; ix = lane * 4 + 1; }
        if (v.z > mv) { mv = v.z; ix = lane * 4 + 2; }
        if (v.w > mv) { mv = v.w; ix = lane * 4 + 3; }
#pragma unroll
        for (int o = 16; o; o >>= 1) {
            float ov = __shfl_xor_sync(0xffffffffu, mv, o);
            int   oi = __shfl_xor_sync(0xffffffffu, ix, o);
            if (ov > mv || (ov == mv && oi < ix)) { mv = ov; ix = oi; }
        }
        m[p] = mv; mi[p] = ix;
    }
    if (lane == 0) {
        float s = m[0] + m[1];
        gate[gw] = s > 0.f ? s : 0.f;
        idxE[gw] = mi[0] * NKEYS + mi[1];
    }
}

// ---------------- K5: expert-in: lin dots + rank-1 adds + exact GELU -------------
__global__ __launch_bounds__(256)
void k_expert_in(const float* __restrict__ x, const float* __restrict__ in_a,
                 const float* __restrict__ in_b, const float* __restrict__ gate,
                 const int* __restrict__ idxE, float* __restrict__ hid) {
    int t = blockIdx.x, tid = threadIdx.x;
    __shared__ float red[8][8];
    __shared__ float linS[8];
    __shared__ int   idxS[8];
    __shared__ float gS[8];
    if (tid < 8) { idxS[tid] = idxE[t * 8 + tid]; gS[tid] = gate[t * 8 + tid]; }
    __syncthreads();

    const float4 xv = *(const float4*)(x + (size_t)t * DIMX + tid * 4);
    float part[8];
#pragma unroll
    for (int h = 0; h < 8; h++) {
        const float4 a = *(const float4*)(in_a + (size_t)idxS[h] * DIMX + tid * 4);
        part[h] = xv.x * a.x + xv.y * a.y + xv.z * a.z + xv.w * a.w;
    }
    int lane = tid & 31, wid = tid >> 5;
#pragma unroll
    for (int h = 0; h < 8; h++) {
        float v = part[h];
#pragma unroll
        for (int o = 16; o; o >>= 1) v += __shfl_xor_sync(0xffffffffu, v, o);
        if (lane == 0) red[h][wid] = v;
    }
    __syncthreads();
    if (tid < 8) {
        float s = 0.f;
#pragma unroll
        for (int j = 0; j < 8; j++) s += red[tid][j];
        linS[tid] = gS[tid] * s;
    }
    __syncthreads();

    int c = tid * 8;
    float acc[8] = {0, 0, 0, 0, 0, 0, 0, 0};
#pragma unroll
    for (int h = 0; h < 8; h++) {
        float lh = linS[h];
        const float4* bp = (const float4*)(in_b + (size_t)idxS[h] * DINNER + c);
        float4 u = bp[0], w2 = bp[1];
        acc[0] += lh * u.x;  acc[1] += lh * u.y;  acc[2] += lh * u.z;  acc[3] += lh * u.w;
        acc[4] += lh * w2.x; acc[5] += lh * w2.y; acc[6] += lh * w2.z; acc[7] += lh * w2.w;
    }
    float* hp = hid + (size_t)t * DINNER + c;
#pragma unroll
    for (int j = 0; j < 8; j++) {
        float v = hp[j] + acc[j];
        hp[j] = 0.5f * v * (1.0f + erff(v * 0.7071067811865476f));
    }
}

// ---------------- K7: expert-out: lout dots + rank-1 adds into d_out -------------
__global__ __launch_bounds__(256)
void k_expert_out(const float* __restrict__ hid, const float* __restrict__ out_a,
                  const float* __restrict__ out_b, const float* __restrict__ gate,
                  const int* __restrict__ idxE, float* __restrict__ out) {
    int t = blockIdx.x, tid = threadIdx.x;
    __shared__ float red[8][8];
    __shared__ float loutS[8];
    __shared__ int   idxS[8];
    __shared__ float gS[8];
    if (tid < 8) { idxS[tid] = idxE[t * 8 + tid]; gS[tid] = gate[t * 8 + tid]; }
    __syncthreads();

    const float4* hp4 = (const float4*)(hid + (size_t)t * DINNER + tid * 8);
    const float4 hv0 = hp4[0], hv1 = hp4[1];
    float part[8];
#pragma unroll
    for (int h = 0; h < 8; h++) {
        const float4* ap = (const float4*)(out_a + (size_t)idxS[h] * DINNER + tid * 8);
        float4 a0 = ap[0], a1 = ap[1];
        part[h] = hv0.x * a0.x + hv0.y * a0.y + hv0.z * a0.z + hv0.w * a0.w
                + hv1.x * a1.x + hv1.y * a1.y + hv1.z * a1.z + hv1.w * a1.w;
    }
    int lane = tid & 31, wid = tid >> 5;
#pragma unroll
    for (int h = 0; h < 8; h++) {
        float v = part[h];
#pragma unroll
        for (int o = 16; o; o >>= 1) v += __shfl_xor_sync(0xffffffffu, v, o);
        if (lane == 0) red[h][wid] = v;
    }
    __syncthreads();
    if (tid < 8) {
        float s = 0.f;
#pragma unroll
        for (int j = 0; j < 8; j++) s += red[tid][j];
        loutS[tid] = gS[tid] * s;
    }
    __syncthreads();

    int c = tid * 4;
    float acc[4] = {0, 0, 0, 0};
#pragma unroll
    for (int h = 0; h < 8; h++) {
        float lh = loutS[h];
        const float4 b = *(const float4*)(out_b + (size_t)idxS[h] * DIMX + c);
        acc[0] += lh * b.x; acc[1] += lh * b.y; acc[2] += lh * b.z; acc[3] += lh * b.w;
    }
    float* op = out + (size_t)t * DIMX + c;
#pragma unroll
    for (int j = 0; j < 4; j++) op[j] += acc[j];
}

// ---------------- launch ----------------
extern "C" void kernel_launch(void* const* d_in, const int* in_sizes, int n_in,
                              void* d_out, int out_size) {
    const float* x     = (const float*)d_in[0];
    const float* Wq    = (const float*)d_in[1];
    const float* keys  = (const float*)d_in[2];
    const float* W_in  = (const float*)d_in[3];
    const float* W_out = (const float*)d_in[4];
    const float* in_a  = (const float*)d_in[5];
    const float* in_b  = (const float*)d_in[6];
    const float* out_a = (const float*)d_in[7];
    const float* out_b = (const float*)d_in[8];
    float* out = (float*)d_out;

    float *WqT, *Mmat, *sim, *hid, *gate; int* idx;
    cudaGetSymbolAddress((void**)&WqT,  g_WqT);
    cudaGetSymbolAddress((void**)&Mmat, g_Mmat);
    cudaGetSymbolAddress((void**)&sim,  g_sim);
    cudaGetSymbolAddress((void**)&hid,  g_hid);
    cudaGetSymbolAddress((void**)&gate, g_gate);
    cudaGetSymbolAddress((void**)&idx,  g_idx);

    // K0: WqT = Wq^T
    k_transpose<<<dim3(32, 256), dim3(32, 8)>>>(Wq, WqT);
    // K1: Mmat[p*8+h] = keys[h,:,p,:] @ Wq[p,h]  (routing: 3xTF32)
    k_gemm_nt<3><<<dim3(8, 1, 16), 512>>>(keys, 1024, WqT, 8192, Mmat, 1024, 512, 1);
    // K2: sim = x @ Mmat^T   [8192, 2048]  (routing: 3xTF32)
    k_gemm_nt<3><<<dim3(16, 64, 1), 512>>>(x, 1024, Mmat, 1024, sim, 2048, 1024, 0);
    // K3: gate/idx via per-(t,h) argmax over each product-key half
    k_argmax<<<8192, 256>>>(sim, gate, idx);
    // K4: hid = x @ W_in^T   [8192, 2048]  (value: 2xTF32)
    k_gemm_nt<2><<<dim3(16, 64, 1), 512>>>(x, 1024, W_in, 1024, hid, 2048, 1024, 0);
    // K5: hid = gelu(hid + sum_h lin_h * in_b[idx_h])
    k_expert_in<<<8192, 256>>>(x, in_a, in_b, gate, idx, hid);
    // K6: out = hid @ W_out^T  [8192, 1024]  (value: 2xTF32)
    k_gemm_nt<2><<<dim3(8, 64, 1), 512>>>(hid, 2048, W_out, 2048, out, 1024, 2048, 0);
    // K7: out += sum_h lout_h * out_b[idx_h]
    k_expert_out<<<8192, 256>>>(hid, out_a, out_b, gate, idx, out);
}

// round 14
// speedup vs baseline: 1.5957x; 1.5957x over previous
#include <cuda_runtime.h>
#include <math.h>

#define TOKENS 8192
#define DIMX   1024
#define HEADS  8
#define NKEYS  128
#define DKEY   512
#define DINNER 2048

// ---------------- scratch (device globals; no allocation allowed) ----------------
__device__ float g_WqT[(size_t)DIMX * 8192];        // 32 MB  (Wq transposed: [1024, 8192])
__device__ float g_Mmat[(size_t)2048 * DIMX];       // 8 MB   (combined key-query matrix)
__device__ float g_sim[(size_t)TOKENS * 2048];      // 64 MB
__device__ float g_hid[(size_t)TOKENS * DINNER];    // 64 MB  (hidden GEMM out, then gelu'd hidden)
__device__ float g_gate[TOKENS * HEADS];
__device__ int   g_idx[TOKENS * HEADS];

// ---------------- helpers ----------------
// 3xTF32 split: f = hi + lo with hi,lo tf32-representable; residual error ~2^-22.
__device__ __forceinline__ void split_tf32(float f, unsigned& hi, unsigned& lo) {
    asm("cvt.rna.tf32.f32 %0, %1;" : "=r"(hi) : "f"(f));
    float r = f - __uint_as_float(hi);   // exact in fp32
    asm("cvt.rna.tf32.f32 %0, %1;" : "=r"(lo) : "f"(r));
}
__device__ __forceinline__ unsigned f2t(float f) {
    unsigned u; asm("cvt.rna.tf32.f32 %0, %1;" : "=r"(u) : "f"(f)); return u;
}
__device__ __forceinline__ void mma8(float c[4], const unsigned a[4], const unsigned b[2]) {
    asm volatile(
        "mma.sync.aligned.m16n8k8.row.col.f32.tf32.tf32.f32 "
        "{%0,%1,%2,%3},{%4,%5,%6,%7},{%8,%9},{%0,%1,%2,%3};"
        : "+f"(c[0]), "+f"(c[1]), "+f"(c[2]), "+f"(c[3])
        : "r"(a[0]), "r"(a[1]), "r"(a[2]), "r"(a[3]), "r"(b[0]), "r"(b[1]));
}

// ---------------- K0: transpose Wq [8192,1024] -> WqT [1024,8192] ----------------
__global__ void k_transpose(const float* __restrict__ src, float* __restrict__ dst) {
    __shared__ float tile[32][33];
    int bx = blockIdx.x * 32, by = blockIdx.y * 32;
    int tx = threadIdx.x, ty = threadIdx.y;   // 32 x 8
#pragma unroll
    for (int j = 0; j < 32; j += 8)
        tile[ty + j][tx] = src[(size_t)(by + ty + j) * 1024 + bx + tx];
    __syncthreads();
#pragma unroll
    for (int j = 0; j < 32; j += 8)
        dst[(size_t)(bx + ty + j) * 8192 + by + tx] = tile[tx][ty + j];
}

// ---------------- NSxTF32 NT GEMM: C[M,N] = A[M,K] * B[N,K]^T --------------------
// BM=128, BN=64, BK=32, 256 threads (8 warps, 4x2), warp tile 32x32 (m16n8k8).
// STATIC smem 27.6KB + <=128 regs -> 2 CTAs/SM: one CTA's bar/LDG windows overlap
// with the other CTA's mma stream (occupancy fix for single-buffer pipeline).
// Reader-side hi/lo split (proven R6 arithmetic).
// NS=3: hh + hl + lh  (routing path, fp32-level accuracy)
// NS=2: hh + hl       (value path, ~2.8e-4 rel; A lo split+mma skipped)
// special==1: batched key->M precompute. z = p*8+h.
template<int NS>
__global__ __launch_bounds__(256, 2)
void k_gemm_nt(const float* __restrict__ A, int lda,
               const float* __restrict__ B, int ldb,
               float* __restrict__ C, int ldc,
               int K, int special) {
    __shared__ float As[128][36];
    __shared__ float Bs[64][36];
    int tid  = threadIdx.x;
    int lane = tid & 31, wid = tid >> 5;
    int g = lane >> 2, tg = lane & 3;
    int wm = (wid >> 1) * 32, wn = (wid & 1) * 32;

    size_t aOff = 0, bOff = 0, cOff = 0;
    if (special) {
        int z = blockIdx.z;                       // z = p*8 + h
        aOff = (size_t)(z & 7) * (128 * 2 * 512)  // head offset in keys
             + (size_t)(z >> 3) * 512;            // p offset
        bOff = (size_t)z * 512;                   // column block in WqT
        cOff = (size_t)z * (128 * 1024);          // row block in Mmat
    }
    const float* Ab = A + aOff + (size_t)(blockIdx.y * 128) * lda;
    const float* Bb = B + bOff + (size_t)(blockIdx.x * 64) * ldb;

    int r0 = tid >> 3;            // 0..31
    int c0 = (tid & 7) * 4;       // 0..28

    // prefetch registers: A rows r0, r0+32, r0+64, r0+96 ; B rows r0, r0+32
    float4 pa0 = *(const float4*)(Ab + (size_t)r0 * lda + c0);
    float4 pa1 = *(const float4*)(Ab + (size_t)(r0 + 32) * lda + c0);
    float4 pa2 = *(const float4*)(Ab + (size_t)(r0 + 64) * lda + c0);
    float4 pa3 = *(const float4*)(Ab + (size_t)(r0 + 96) * lda + c0);
    float4 pb0 = *(const float4*)(Bb + (size_t)r0 * ldb + c0);
    float4 pb1 = *(const float4*)(Bb + (size_t)(r0 + 32) * ldb + c0);

    float acc[2][4][4];
#pragma unroll
    for (int i = 0; i < 2; i++)
#pragma unroll
        for (int j = 0; j < 4; j++)
#pragma unroll
            for (int k = 0; k < 4; k++) acc[i][j][k] = 0.f;

    int KT = K >> 5;
    for (int kt = 0; kt < KT; kt++) {
        *(float4*)&As[r0][c0]      = pa0;
        *(float4*)&As[r0 + 32][c0] = pa1;
        *(float4*)&As[r0 + 64][c0] = pa2;
        *(float4*)&As[r0 + 96][c0] = pa3;
        *(float4*)&Bs[r0][c0]      = pb0;
        *(float4*)&Bs[r0 + 32][c0] = pb1;
        __syncthreads();

        if (kt + 1 < KT) {        // prefetch next tile; overlaps with compute below
            const float* Ap = Ab + (size_t)(kt + 1) * 32;
            const float* Bp = Bb + (size_t)(kt + 1) * 32;
            pa0 = *(const float4*)(Ap + (size_t)r0 * lda + c0);
            pa1 = *(const float4*)(Ap + (size_t)(r0 + 32) * lda + c0);
            pa2 = *(const float4*)(Ap + (size_t)(r0 + 64) * lda + c0);
            pa3 = *(const float4*)(Ap + (size_t)(r0 + 96) * lda + c0);
            pb0 = *(const float4*)(Bp + (size_t)r0 * ldb + c0);
            pb1 = *(const float4*)(Bp + (size_t)(r0 + 32) * ldb + c0);
        }

#pragma unroll
        for (int ks = 0; ks < 4; ks++) {
            int k0 = ks * 8;
            unsigned ah[2][4], al[2][4], bh[4][2], bl[4][2];
#pragma unroll
            for (int mt = 0; mt < 2; mt++) {
                int rr = wm + mt * 16 + g;
                if (NS >= 3) {
                    split_tf32(As[rr][k0 + tg],         ah[mt][0], al[mt][0]);
                    split_tf32(As[rr + 8][k0 + tg],     ah[mt][1], al[mt][1]);
                    split_tf32(As[rr][k0 + tg + 4],     ah[mt][2], al[mt][2]);
                    split_tf32(As[rr + 8][k0 + tg + 4], ah[mt][3], al[mt][3]);
                } else {
                    ah[mt][0] = f2t(As[rr][k0 + tg]);
                    ah[mt][1] = f2t(As[rr + 8][k0 + tg]);
                    ah[mt][2] = f2t(As[rr][k0 + tg + 4]);
                    ah[mt][3] = f2t(As[rr + 8][k0 + tg + 4]);
                }
            }
#pragma unroll
            for (int nt = 0; nt < 4; nt++) {
                int nn = wn + nt * 8 + g;
                split_tf32(Bs[nn][k0 + tg],     bh[nt][0], bl[nt][0]);
                split_tf32(Bs[nn][k0 + tg + 4], bh[nt][1], bl[nt][1]);
            }
#pragma unroll
            for (int mt = 0; mt < 2; mt++)
#pragma unroll
                for (int nt = 0; nt < 4; nt++) {
                    mma8(acc[mt][nt], ah[mt], bh[nt]);                 // hi*hi
                    mma8(acc[mt][nt], ah[mt], bl[nt]);                 // hi*lo
                    if (NS >= 3) mma8(acc[mt][nt], al[mt], bh[nt]);    // lo*hi
                }
        }
        __syncthreads();
    }

    float* Cb = C + cOff + (size_t)(blockIdx.y * 128) * ldc + blockIdx.x * 64;
#pragma unroll
    for (int mt = 0; mt < 2; mt++)
#pragma unroll
        for (int nt = 0; nt < 4; nt++) {
            int rr = wm + mt * 16 + g;
            int cc = wn + nt * 8 + 2 * tg;
            *(float2*)(Cb + (size_t)rr * ldc + cc) =
                make_float2(acc[mt][nt][0], acc[mt][nt][1]);
            *(float2*)(Cb + (size_t)(rr + 8) * ldc + cc) =
                make_float2(acc[mt][nt][2], acc[mt][nt][3]);
        }
}

// ---------------- K3: argmax over 128 keys per (t,h,p); gate + expert index ------
// top1 of (sx_i+sy_j) over the 16x16 topk cross product == max(sx)+max(sy).
__global__ void k_argmax(const float* __restrict__ sim,
                         float* __restrict__ gate, int* __restrict__ idxE) {
    int gw = (blockIdx.x * blockDim.x + threadIdx.x) >> 5;
    int lane = threadIdx.x & 31;
    if (gw >= TOKENS * HEADS) return;
    int t = gw >> 3, h = gw & 7;
    const float* p0 = sim + (size_t)t * 2048 + h * 128;
    float m[2]; int mi[2];
#pragma unroll
    for (int p = 0; p < 2; p++) {
        const float4 v = *(const float4*)(p0 + p * 1024 + lane * 4);
        float mv = v.x; int ix = lane * 4;
        if (v.y > mv) { mv = v.y; ix = lane * 4 + 1; }
        if (v.z > mv) { mv = v.z; ix = lane * 4 + 2; }
        if (v.w > mv) { mv = v.w; ix = lane * 4 + 3; }
#pragma unroll
        for (int o = 16; o; o >>= 1) {
            float ov = __shfl_xor_sync(0xffffffffu, mv, o);
            int   oi = __shfl_xor_sync(0xffffffffu, ix, o);
            if (ov > mv || (ov == mv && oi < ix)) { mv = ov; ix = oi; }
        }
        m[p] = mv; mi[p] = ix;
    }
    if (lane == 0) {
        float s = m[0] + m[1];
        gate[gw] = s > 0.f ? s : 0.f;
        idxE[gw] = mi[0] * NKEYS + mi[1];
    }
}

// ---------------- K5: expert-in: lin dots + rank-1 adds + exact GELU -------------
__global__ __launch_bounds__(256)
void k_expert_in(const float* __restrict__ x, const float* __restrict__ in_a,
                 const float* __restrict__ in_b, const float* __restrict__ gate,
                 const int* __restrict__ idxE, float* __restrict__ hid) {
    int t = blockIdx.x, tid = threadIdx.x;
    __shared__ float red[8][8];
    __shared__ float linS[8];
    __shared__ int   idxS[8];
    __shared__ float gS[8];
    if (tid < 8) { idxS[tid] = idxE[t * 8 + tid]; gS[tid] = gate[t * 8 + tid]; }
    __syncthreads();

    const float4 xv = *(const float4*)(x + (size_t)t * DIMX + tid * 4);
    float part[8];
#pragma unroll
    for (int h = 0; h < 8; h++) {
        const float4 a = *(const float4*)(in_a + (size_t)idxS[h] * DIMX + tid * 4);
        part[h] = xv.x * a.x + xv.y * a.y + xv.z * a.z + xv.w * a.w;
    }
    int lane = tid & 31, wid = tid >> 5;
#pragma unroll
    for (int h = 0; h < 8; h++) {
        float v = part[h];
#pragma unroll
        for (int o = 16; o; o >>= 1) v += __shfl_xor_sync(0xffffffffu, v, o);
        if (lane == 0) red[h][wid] = v;
    }
    __syncthreads();
    if (tid < 8) {
        float s = 0.f;
#pragma unroll
        for (int j = 0; j < 8; j++) s += red[tid][j];
        linS[tid] = gS[tid] * s;
    }
    __syncthreads();

    int c = tid * 8;
    float acc[8] = {0, 0, 0, 0, 0, 0, 0, 0};
#pragma unroll
    for (int h = 0; h < 8; h++) {
        float lh = linS[h];
        const float4* bp = (const float4*)(in_b + (size_t)idxS[h] * DINNER + c);
        float4 u = bp[0], w2 = bp[1];
        acc[0] += lh * u.x;  acc[1] += lh * u.y;  acc[2] += lh * u.z;  acc[3] += lh * u.w;
        acc[4] += lh * w2.x; acc[5] += lh * w2.y; acc[6] += lh * w2.z; acc[7] += lh * w2.w;
    }
    float* hp = hid + (size_t)t * DINNER + c;
#pragma unroll
    for (int j = 0; j < 8; j++) {
        float v = hp[j] + acc[j];
        hp[j] = 0.5f * v * (1.0f + erff(v * 0.7071067811865476f));
    }
}

// ---------------- K7: expert-out: lout dots + rank-1 adds into d_out -------------
__global__ __launch_bounds__(256)
void k_expert_out(const float* __restrict__ hid, const float* __restrict__ out_a,
                  const float* __restrict__ out_b, const float* __restrict__ gate,
                  const int* __restrict__ idxE, float* __restrict__ out) {
    int t = blockIdx.x, tid = threadIdx.x;
    __shared__ float red[8][8];
    __shared__ float loutS[8];
    __shared__ int   idxS[8];
    __shared__ float gS[8];
    if (tid < 8) { idxS[tid] = idxE[t * 8 + tid]; gS[tid] = gate[t * 8 + tid]; }
    __syncthreads();

    const float4* hp4 = (const float4*)(hid + (size_t)t * DINNER + tid * 8);
    const float4 hv0 = hp4[0], hv1 = hp4[1];
    float part[8];
#pragma unroll
    for (int h = 0; h < 8; h++) {
        const float4* ap = (const float4*)(out_a + (size_t)idxS[h] * DINNER + tid * 8);
        float4 a0 = ap[0], a1 = ap[1];
        part[h] = hv0.x * a0.x + hv0.y * a0.y + hv0.z * a0.z + hv0.w * a0.w
                + hv1.x * a1.x + hv1.y * a1.y + hv1.z * a1.z + hv1.w * a1.w;
    }
    int lane = tid & 31, wid = tid >> 5;
#pragma unroll
    for (int h = 0; h < 8; h++) {
        float v = part[h];
#pragma unroll
        for (int o = 16; o; o >>= 1) v += __shfl_xor_sync(0xffffffffu, v, o);
        if (lane == 0) red[h][wid] = v;
    }
    __syncthreads();
    if (tid < 8) {
        float s = 0.f;
#pragma unroll
        for (int j = 0; j < 8; j++) s += red[tid][j];
        loutS[tid] = gS[tid] * s;
    }
    __syncthreads();

    int c = tid * 4;
    float acc[4] = {0, 0, 0, 0};
#pragma unroll
    for (int h = 0; h < 8; h++) {
        float lh = loutS[h];
        const float4 b = *(const float4*)(out_b + (size_t)idxS[h] * DIMX + c);
        acc[0] += lh * b.x; acc[1] += lh * b.y; acc[2] += lh * b.z; acc[3] += lh * b.w;
    }
    float* op = out + (size_t)t * DIMX + c;
#pragma unroll
    for (int j = 0; j < 4; j++) op[j] += acc[j];
}

// ---------------- launch ----------------
extern "C" void kernel_launch(void* const* d_in, const int* in_sizes, int n_in,
                              void* d_out, int out_size) {
    const float* x     = (const float*)d_in[0];
    const float* Wq    = (const float*)d_in[1];
    const float* keys  = (const float*)d_in[2];
    const float* W_in  = (const float*)d_in[3];
    const float* W_out = (const float*)d_in[4];
    const float* in_a  = (const float*)d_in[5];
    const float* in_b  = (const float*)d_in[6];
    const float* out_a = (const float*)d_in[7];
    const float* out_b = (const float*)d_in[8];
    float* out = (float*)d_out;

    float *WqT, *Mmat, *sim, *hid, *gate; int* idx;
    cudaGetSymbolAddress((void**)&WqT,  g_WqT);
    cudaGetSymbolAddress((void**)&Mmat, g_Mmat);
    cudaGetSymbolAddress((void**)&sim,  g_sim);
    cudaGetSymbolAddress((void**)&hid,  g_hid);
    cudaGetSymbolAddress((void**)&gate, g_gate);
    cudaGetSymbolAddress((void**)&idx,  g_idx);

    // K0: WqT = Wq^T
    k_transpose<<<dim3(32, 256), dim3(32, 8)>>>(Wq, WqT);
    // K1: Mmat[p*8+h] = keys[h,:,p,:] @ Wq[p,h]  (routing: 3xTF32)
    k_gemm_nt<3><<<dim3(16, 1, 16), 256>>>(keys, 1024, WqT, 8192, Mmat, 1024, 512, 1);
    // K2: sim = x @ Mmat^T   [8192, 2048]  (routing: 3xTF32)
    k_gemm_nt<3><<<dim3(32, 64, 1), 256>>>(x, 1024, Mmat, 1024, sim, 2048, 1024, 0);
    // K3: gate/idx via per-(t,h) argmax over each product-key half
    k_argmax<<<8192, 256>>>(sim, gate, idx);
    // K4: hid = x @ W_in^T   [8192, 2048]  (value: 2xTF32)
    k_gemm_nt<2><<<dim3(32, 64, 1), 256>>>(x, 1024, W_in, 1024, hid, 2048, 1024, 0);
    // K5: hid = gelu(hid + sum_h lin_h * in_b[idx_h])
    k_expert_in<<<8192, 256>>>(x, in_a, in_b, gate, idx, hid);
    // K6: out = hid @ W_out^T  [8192, 1024]  (value: 2xTF32)
    k_gemm_nt<2><<<dim3(16, 64, 1), 256>>>(hid, 2048, W_out, 2048, out, 1024, 2048, 0);
    // K7: out += sum_h lout_h * out_b[idx_h]
    k_expert_out<<<8192, 256>>>(hid, out_a, out_b, gate, idx, out);
}